// round 1
// baseline (speedup 1.0000x reference)
#include <cuda_runtime.h>

// Problem constants: B=2, C=128, IC=64, W=H=32, Z=128, nz=64
// n = B*W*H = 2048 z-line tiles of x: (C=128) x (Z=128), z contiguous.

#define N_TILES   2048
#define THREADS   256

// ---- device-global precomputed buffers (setup kernel fills them) ----
__device__ float d_vt[128];       // cat_w[:64]^T @ theta_w  (collapses theta conv)
__device__ float d_ct;            // cat_w[:64] . theta_b
__device__ float d_alpha[128];    // bn_g / sqrt(bn_v + eps)
__device__ float d_beta[128];     // (W_b - bn_m)*alpha + bn_b
__device__ float d_gpwT[16384];   // row Ci: [g_w[oc][Ci] for oc 0..63 | phi_w[oc][Ci] for oc 0..63]
__device__ float d_WwT[8192];     // row c:  [W_w[Co][c] for Co 0..127]

__global__ void setup_kernel(const float* __restrict__ theta_w,
                             const float* __restrict__ theta_b,
                             const float* __restrict__ cat_w,
                             const float* __restrict__ W_b,
                             const float* __restrict__ bn_g,
                             const float* __restrict__ bn_b,
                             const float* __restrict__ bn_m,
                             const float* __restrict__ bn_v,
                             const float* __restrict__ g_w,
                             const float* __restrict__ phi_w,
                             const float* __restrict__ W_w)
{
    int tid = threadIdx.x;  // 256 threads, 1 block
    if (tid < 128) {
        float s = 0.f;
        for (int ic = 0; ic < 64; ic++) s += cat_w[ic] * theta_w[ic * 128 + tid];
        d_vt[tid] = s;
        float a = bn_g[tid] * rsqrtf(bn_v[tid] + 1e-5f);
        d_alpha[tid] = a;
        d_beta[tid]  = (W_b[tid] - bn_m[tid]) * a + bn_b[tid];
    }
    if (tid == 0) {
        float s = 0.f;
        for (int ic = 0; ic < 64; ic++) s += cat_w[ic] * theta_b[ic];
        d_ct = s;
    }
    // transpose g_w / phi_w : (64 oc, 128 C) -> rows of C with oc contiguous
    for (int idx = tid; idx < 8192; idx += 256) {
        int oc = idx >> 7, Ci = idx & 127;
        d_gpwT[Ci * 128 + oc]       = g_w[idx];
        d_gpwT[Ci * 128 + 64 + oc]  = phi_w[idx];
    }
    // transpose W_w : (128 Co, 64 c) -> rows of c with Co contiguous
    for (int idx = tid; idx < 8192; idx += 256) {
        int Co = idx >> 6, c = idx & 63;
        d_WwT[c * 128 + Co] = W_w[idx];
    }
}

// Shared memory layout (floats)
#define OFF_XS     0        // 16384 : x tile [C=128][Z=128]
#define OFF_GPWT   16384    // 16384 : g|phi weights transposed [C=128][128]
#define OFF_WWT    32768    //  8192 : W weights transposed [c=64][Co=128]
#define OFF_YS     40960    //  8192 : y transposed [c=64][i=128]
#define OFF_GP     49152    //  4096 : pooled g [j=64][c=64]
#define OFF_BBP    53248    //   512 : per-warp partials of bb [wid=8][j=64]
#define OFF_A      53760    //   128 : a[i]
#define OFF_BB     53888    //    64 : bb[j]
#define OFF_VT     53952    //   128
#define OFF_WP     54080    //    64 : cat_w[64:]
#define OFF_GB     54144    //    64 : g_b
#define OFF_PB     54208    //    64 : phi_b
#define OFF_AL     54272    //   128 : alpha
#define OFF_BE     54400    //   128 : beta
#define SMEM_FLOATS 54528
#define SMEM_BYTES (SMEM_FLOATS * 4)   // 218112

__global__ void __launch_bounds__(THREADS, 1)
nonlocal_kernel(const float* __restrict__ x,
                const float* __restrict__ g_b,
                const float* __restrict__ phi_b,
                const float* __restrict__ cat_w,
                float* __restrict__ out)
{
    extern __shared__ float sm[];
    float*       xs   = sm + OFF_XS;
    float*       gp   = sm + OFF_GP;
    float*       bbp  = sm + OFF_BBP;
    float*       a_s  = sm + OFF_A;
    float*       bb_s = sm + OFF_BB;
    float*       vt_s = sm + OFF_VT;
    float*       wp_s = sm + OFF_WP;
    float*       gb_s = sm + OFF_GB;
    float*       pb_s = sm + OFF_PB;
    float*       al_s = sm + OFF_AL;
    float*       be_s = sm + OFF_BE;
    float4*      xs4    = (float4*)(sm + OFF_XS);
    float4*      gpwT4  = (float4*)(sm + OFF_GPWT);
    float4*      WwT4   = (float4*)(sm + OFF_WWT);
    float4*      ys4    = (float4*)(sm + OFF_YS);
    const float4* gp4   = (const float4*)(sm + OFF_GP);

    const int tid  = threadIdx.x;
    const int lane = tid & 31;
    const int wid  = tid >> 5;

    const int n  = blockIdx.x;       // tile id
    const int b  = n >> 10;
    const int wh = n & 1023;

    // x[b][c][wh][z]: float offset ((b*128 + c)*1024 + wh)*128 + z
    const float4* xg = (const float4*)(x + (((size_t)(b * 128) * 1024 + wh) * 128));

    // ---- stage A: loads (all coalesced float4, conflict-free smem stores) ----
    #pragma unroll
    for (int it = 0; it < 16; it++) {
        int idx = it * 256 + tid;              // 4096 float4
        int c = idx >> 5, zq = idx & 31;
        xs4[idx] = xg[(size_t)c * 32768 + zq]; // row stride 131072 floats
    }
    {
        const float4* gg = (const float4*)d_gpwT;
        #pragma unroll
        for (int it = 0; it < 16; it++) gpwT4[it * 256 + tid] = gg[it * 256 + tid];
        const float4* wg = (const float4*)d_WwT;
        #pragma unroll
        for (int it = 0; it < 8; it++)  WwT4[it * 256 + tid] = wg[it * 256 + tid];
    }
    if (tid < 128) { vt_s[tid] = d_vt[tid]; al_s[tid] = d_alpha[tid]; be_s[tid] = d_beta[tid]; }
    if (tid < 64)  { wp_s[tid] = cat_w[64 + tid]; gb_s[tid] = g_b[tid]; pb_s[tid] = phi_b[tid]; }
    __syncthreads();

    // ---- stage B: g-conv + phi-conv + a, register-blocked 4z x 8oc per thread ----
    // warp wid -> oc = wid*8 .. wid*8+7 ; lane -> z = 4*lane .. 4*lane+3
    float ga[4][8], pa[4][8], aa[4];
    #pragma unroll
    for (int k = 0; k < 4; k++) {
        aa[k] = 0.f;
        #pragma unroll
        for (int o = 0; o < 8; o++) { ga[k][o] = 0.f; pa[k][o] = 0.f; }
    }

    #pragma unroll 2
    for (int Ci = 0; Ci < 128; Ci++) {
        float4 xv = xs4[Ci * 32 + lane];
        float4 G0 = gpwT4[Ci * 32 + (wid << 1)];
        float4 G1 = gpwT4[Ci * 32 + (wid << 1) + 1];
        float4 P0 = gpwT4[Ci * 32 + 16 + (wid << 1)];
        float4 P1 = gpwT4[Ci * 32 + 17 + (wid << 1)];
        float xk[4] = {xv.x, xv.y, xv.z, xv.w};
        float gw[8] = {G0.x, G0.y, G0.z, G0.w, G1.x, G1.y, G1.z, G1.w};
        float pw[8] = {P0.x, P0.y, P0.z, P0.w, P1.x, P1.y, P1.z, P1.w};
        #pragma unroll
        for (int k = 0; k < 4; k++) {
            #pragma unroll
            for (int o = 0; o < 8; o++) {
                ga[k][o] = fmaf(xk[k], gw[o], ga[k][o]);
                pa[k][o] = fmaf(xk[k], pw[o], pa[k][o]);
            }
        }
        if (wid == 0) {   // warp 0 also computes a[i] = vt . x[:,i]  (collapsed theta)
            float v = vt_s[Ci];
            #pragma unroll
            for (int k = 0; k < 4; k++) aa[k] = fmaf(v, xk[k], aa[k]);
        }
    }

    // bias, maxpool z-pairs, write gp[j][c], bb warp-partials, a[i]
    {
        const int oc = wid * 8;
        const int j0 = lane * 2, j1 = lane * 2 + 1;
        float part0 = 0.f, part1 = 0.f;
        #pragma unroll
        for (int o = 0; o < 8; o++) {
            float gb = gb_s[oc + o], pb = pb_s[oc + o];
            gp[j0 * 64 + oc + o] = fmaxf(ga[0][o] + gb, ga[1][o] + gb);
            gp[j1 * 64 + oc + o] = fmaxf(ga[2][o] + gb, ga[3][o] + gb);
            float p01 = fmaxf(pa[0][o] + pb, pa[1][o] + pb);
            float p23 = fmaxf(pa[2][o] + pb, pa[3][o] + pb);
            float wpv = wp_s[oc + o];
            part0 = fmaf(wpv, p01, part0);
            part1 = fmaf(wpv, p23, part1);
        }
        bbp[wid * 64 + j0] = part0;
        bbp[wid * 64 + j1] = part1;
        if (wid == 0) {
            float ct = d_ct;
            #pragma unroll
            for (int k = 0; k < 4; k++) a_s[lane * 4 + k] = aa[k] + ct;
        }
    }
    __syncthreads();

    if (tid < 64) {  // deterministic reduction of bb over the 8 warps
        float s = 0.f;
        #pragma unroll
        for (int w8 = 0; w8 < 8; w8++) s += bbp[w8 * 64 + tid];
        bb_s[tid] = s;
    }
    __syncthreads();

    // ---- stage C: y[i][c] = sum_j relu(a[i]+bb[j])/64 * gp[j][c] ----
    // warp wid -> c = wid*8..+7 ; lane -> i = 4*lane..+3
    {
        float ya[4][8];
        #pragma unroll
        for (int k = 0; k < 4; k++)
            #pragma unroll
            for (int o = 0; o < 8; o++) ya[k][o] = 0.f;

        float4 av = ((const float4*)a_s)[lane];
        float ak[4] = {av.x, av.y, av.z, av.w};

        #pragma unroll 4
        for (int j = 0; j < 64; j++) {
            float bj = bb_s[j];
            float f0 = fmaxf(ak[0] + bj, 0.f) * 0.015625f;
            float f1 = fmaxf(ak[1] + bj, 0.f) * 0.015625f;
            float f2 = fmaxf(ak[2] + bj, 0.f) * 0.015625f;
            float f3 = fmaxf(ak[3] + bj, 0.f) * 0.015625f;
            float4 g0 = gp4[j * 16 + (wid << 1)];
            float4 g1 = gp4[j * 16 + (wid << 1) + 1];
            float gv[8] = {g0.x, g0.y, g0.z, g0.w, g1.x, g1.y, g1.z, g1.w};
            float fk[4] = {f0, f1, f2, f3};
            #pragma unroll
            for (int k = 0; k < 4; k++)
                #pragma unroll
                for (int o = 0; o < 8; o++)
                    ya[k][o] = fmaf(fk[k], gv[o], ya[k][o]);
        }
        const int ocy = wid * 8;
        #pragma unroll
        for (int o = 0; o < 8; o++)  // ys stored transposed: [c][i], i contiguous
            ys4[(ocy + o) * 32 + lane] = make_float4(ya[0][o], ya[1][o], ya[2][o], ya[3][o]);
    }
    __syncthreads();

    // ---- stage D: out[Co][i] = alpha[Co]*(sum_c W[Co][c]*y[i][c]) + beta[Co] + x[Co][i] ----
    // warp wid -> Co = wid*16..+15 ; lane -> i = 4*lane..+3
    {
        float oa[16][4];
        #pragma unroll
        for (int cc = 0; cc < 16; cc++)
            #pragma unroll
            for (int k = 0; k < 4; k++) oa[cc][k] = 0.f;

        #pragma unroll 2
        for (int c = 0; c < 64; c++) {
            float4 yv = ys4[c * 32 + lane];
            float yk[4] = {yv.x, yv.y, yv.z, yv.w};
            float4 w0 = WwT4[c * 32 + (wid << 2)];
            float4 w1 = WwT4[c * 32 + (wid << 2) + 1];
            float4 w2 = WwT4[c * 32 + (wid << 2) + 2];
            float4 w3 = WwT4[c * 32 + (wid << 2) + 3];
            float wv[16] = {w0.x, w0.y, w0.z, w0.w, w1.x, w1.y, w1.z, w1.w,
                            w2.x, w2.y, w2.z, w2.w, w3.x, w3.y, w3.z, w3.w};
            #pragma unroll
            for (int cc = 0; cc < 16; cc++)
                #pragma unroll
                for (int k = 0; k < 4; k++)
                    oa[cc][k] = fmaf(wv[cc], yk[k], oa[cc][k]);
        }

        float4* out4 = (float4*)out;
        const int Cb = wid * 16;
        #pragma unroll
        for (int cc = 0; cc < 16; cc++) {
            int Co = Cb + cc;
            float al = al_s[Co], be = be_s[Co];
            float4 xv = xs4[Co * 32 + lane];  // residual
            float4 r;
            r.x = fmaf(oa[cc][0], al, be) + xv.x;
            r.y = fmaf(oa[cc][1], al, be) + xv.y;
            r.z = fmaf(oa[cc][2], al, be) + xv.z;
            r.w = fmaf(oa[cc][3], al, be) + xv.w;
            size_t obase = ((size_t)(b * 128 + Co) * 1024 + wh) * 32 + lane;
            out4[obase] = r;
        }
    }
}

extern "C" void kernel_launch(void* const* d_in, const int* in_sizes, int n_in,
                              void* d_out, int out_size)
{
    const float* x       = (const float*)d_in[0];
    const float* g_w     = (const float*)d_in[1];
    const float* g_b     = (const float*)d_in[2];
    const float* theta_w = (const float*)d_in[3];
    const float* theta_b = (const float*)d_in[4];
    const float* phi_w   = (const float*)d_in[5];
    const float* phi_b   = (const float*)d_in[6];
    const float* cat_w   = (const float*)d_in[7];
    const float* W_w     = (const float*)d_in[8];
    const float* W_b     = (const float*)d_in[9];
    const float* bn_g    = (const float*)d_in[10];
    const float* bn_b    = (const float*)d_in[11];
    const float* bn_m    = (const float*)d_in[12];
    const float* bn_v    = (const float*)d_in[13];

    cudaFuncSetAttribute(nonlocal_kernel,
                         cudaFuncAttributeMaxDynamicSharedMemorySize, SMEM_BYTES);

    setup_kernel<<<1, 256>>>(theta_w, theta_b, cat_w, W_b,
                             bn_g, bn_b, bn_m, bn_v, g_w, phi_w, W_w);
    nonlocal_kernel<<<N_TILES, THREADS, SMEM_BYTES>>>(x, g_b, phi_b, cat_w,
                                                      (float*)d_out);
}

// round 2
// speedup vs baseline: 1.1135x; 1.1135x over previous
#include <cuda_runtime.h>

// Problem constants: B=2, C=128, IC=64, W=H=32, Z=128, nz=64
// n = B*W*H = 2048 z-line tiles of x: (C=128) x (Z=128), z contiguous.

#define N_TILES   2048
#define THREADS   256

// ---- packed f32x2 helpers (SASS FFMA2 — only reachable via PTX) ----
__device__ __forceinline__ unsigned long long pk2(float lo, float hi) {
    unsigned long long r;
    asm("mov.b64 %0, {%1, %2};" : "=l"(r) : "f"(lo), "f"(hi));
    return r;
}
__device__ __forceinline__ void fma2(unsigned long long& d,
                                     unsigned long long a,
                                     unsigned long long b) {
    asm("fma.rn.f32x2 %0, %1, %2, %3;" : "=l"(d) : "l"(a), "l"(b), "l"(d));
}
__device__ __forceinline__ float2 upk2(unsigned long long v) {
    float2 r;
    asm("mov.b64 {%0, %1}, %2;" : "=f"(r.x), "=f"(r.y) : "l"(v));
    return r;
}

// ---- device-global precomputed buffers (setup kernel fills them) ----
__device__ float d_vt[128];       // cat_w[:64]^T @ theta_w  (collapses theta conv)
__device__ float d_ct;            // cat_w[:64] . theta_b
__device__ float d_alpha[128];    // bn_g / sqrt(bn_v + eps)
__device__ float d_beta[128];     // (W_b - bn_m)*alpha + bn_b
__device__ float d_gpwT[16384];   // row Ci: [g_w[oc][Ci] oc 0..63 | phi_w[oc][Ci] oc 0..63]
__device__ float d_WwT[8192];     // row c:  [W_w[Co][c] for Co 0..127]

__global__ void setup_kernel(const float* __restrict__ theta_w,
                             const float* __restrict__ theta_b,
                             const float* __restrict__ cat_w,
                             const float* __restrict__ W_b,
                             const float* __restrict__ bn_g,
                             const float* __restrict__ bn_b,
                             const float* __restrict__ bn_m,
                             const float* __restrict__ bn_v,
                             const float* __restrict__ g_w,
                             const float* __restrict__ phi_w,
                             const float* __restrict__ W_w)
{
    int tid = threadIdx.x;  // 256 threads, 1 block
    if (tid < 128) {
        float s = 0.f;
        for (int ic = 0; ic < 64; ic++) s += cat_w[ic] * theta_w[ic * 128 + tid];
        d_vt[tid] = s;
        float a = bn_g[tid] * rsqrtf(bn_v[tid] + 1e-5f);
        d_alpha[tid] = a;
        d_beta[tid]  = (W_b[tid] - bn_m[tid]) * a + bn_b[tid];
    }
    if (tid == 0) {
        float s = 0.f;
        for (int ic = 0; ic < 64; ic++) s += cat_w[ic] * theta_b[ic];
        d_ct = s;
    }
    for (int idx = tid; idx < 8192; idx += 256) {
        int oc = idx >> 7, Ci = idx & 127;
        d_gpwT[Ci * 128 + oc]       = g_w[idx];
        d_gpwT[Ci * 128 + 64 + oc]  = phi_w[idx];
    }
    for (int idx = tid; idx < 8192; idx += 256) {
        int Co = idx >> 6, c = idx & 63;
        d_WwT[c * 128 + Co] = W_w[idx];
    }
}

// Shared memory layout (floats)
#define OFF_XS     0        // 16384 : x tile [C=128][Z=128]
#define OFF_GPWT   16384    // 16384 : g|phi weights transposed [C=128][128]
#define OFF_WWT    32768    //  8192 : W weights transposed [c=64][Co=128]
#define OFF_YS     40960    //  8192 : y transposed [c=64][i=128]
#define OFF_GP     49152    //  4096 : pooled g (pre-scaled by 1/64) [j=64][c=64]
#define OFF_BBP    53248    //   512 : per-warp partials of bb [wid=8][j=64]
#define OFF_A      53760    //   128 : a[i]
#define OFF_BB     53888    //    64 : bb[j]
#define OFF_VT     53952    //   128
#define OFF_WP     54080    //    64 : cat_w[64:]
#define OFF_GB     54144    //    64 : g_b
#define OFF_PB     54208    //    64 : phi_b
#define OFF_AL     54272    //   128 : alpha
#define OFF_BE     54400    //   128 : beta
#define SMEM_FLOATS 54528
#define SMEM_BYTES (SMEM_FLOATS * 4)   // 218112

__global__ void __launch_bounds__(THREADS, 1)
nonlocal_kernel(const float* __restrict__ x,
                const float* __restrict__ g_b,
                const float* __restrict__ phi_b,
                const float* __restrict__ cat_w,
                float* __restrict__ out)
{
    extern __shared__ float sm[];
    float*       gp   = sm + OFF_GP;
    float*       bbp  = sm + OFF_BBP;
    float*       a_s  = sm + OFF_A;
    float*       bb_s = sm + OFF_BB;
    float*       vt_s = sm + OFF_VT;
    float*       wp_s = sm + OFF_WP;
    float*       gb_s = sm + OFF_GB;
    float*       pb_s = sm + OFF_PB;
    float*       al_s = sm + OFF_AL;
    float*       be_s = sm + OFF_BE;
    float4*      xs4    = (float4*)(sm + OFF_XS);
    float4*      gpwT4  = (float4*)(sm + OFF_GPWT);
    float4*      WwT4   = (float4*)(sm + OFF_WWT);
    float4*      ys4    = (float4*)(sm + OFF_YS);
    const float4* gp4   = (const float4*)(sm + OFF_GP);

    const int tid  = threadIdx.x;
    const int lane = tid & 31;
    const int wid  = tid >> 5;

    const int n  = blockIdx.x;       // tile id
    const int b  = n >> 10;
    const int wh = n & 1023;

    // x[b][c][wh][z]: float offset ((b*128 + c)*1024 + wh)*128 + z
    const float4* xg = (const float4*)(x + (((size_t)(b * 128) * 1024 + wh) * 128));

    // ---- stage A: loads (all coalesced float4, conflict-free smem stores) ----
    #pragma unroll
    for (int it = 0; it < 16; it++) {
        int idx = it * 256 + tid;              // 4096 float4
        int c = idx >> 5, zq = idx & 31;
        xs4[idx] = xg[(size_t)c * 32768 + zq]; // row stride 131072 floats
    }
    {
        const float4* gg = (const float4*)d_gpwT;
        #pragma unroll
        for (int it = 0; it < 16; it++) gpwT4[it * 256 + tid] = gg[it * 256 + tid];
        const float4* wg = (const float4*)d_WwT;
        #pragma unroll
        for (int it = 0; it < 8; it++)  WwT4[it * 256 + tid] = wg[it * 256 + tid];
    }
    if (tid < 128) { vt_s[tid] = d_vt[tid]; al_s[tid] = d_alpha[tid]; be_s[tid] = d_beta[tid]; }
    if (tid < 64)  { wp_s[tid] = cat_w[64 + tid]; gb_s[tid] = g_b[tid]; pb_s[tid] = phi_b[tid]; }
    __syncthreads();

    // ---- stage B: g-conv + phi-conv + a ; packed f32x2 over z-pairs ----
    // warp wid -> oc = wid*8 .. +7 ; lane -> z = 4*lane .. +3 (2 packed pairs)
    unsigned long long ga2[2][8], pa2[2][8], aa2[2];
    #pragma unroll
    for (int kp = 0; kp < 2; kp++) {
        aa2[kp] = 0ULL;
        #pragma unroll
        for (int o = 0; o < 8; o++) { ga2[kp][o] = 0ULL; pa2[kp][o] = 0ULL; }
    }

    #pragma unroll 2
    for (int Ci = 0; Ci < 128; Ci++) {
        ulonglong2 xq = *(const ulonglong2*)&xs4[Ci * 32 + lane];  // (z0,z1),(z2,z3)
        unsigned long long x2[2] = {xq.x, xq.y};
        float4 G0 = gpwT4[Ci * 32 + (wid << 1)];
        float4 G1 = gpwT4[Ci * 32 + (wid << 1) + 1];
        float4 P0 = gpwT4[Ci * 32 + 16 + (wid << 1)];
        float4 P1 = gpwT4[Ci * 32 + 17 + (wid << 1)];
        unsigned long long gw2[8], pw2[8];
        gw2[0] = pk2(G0.x, G0.x); gw2[1] = pk2(G0.y, G0.y);
        gw2[2] = pk2(G0.z, G0.z); gw2[3] = pk2(G0.w, G0.w);
        gw2[4] = pk2(G1.x, G1.x); gw2[5] = pk2(G1.y, G1.y);
        gw2[6] = pk2(G1.z, G1.z); gw2[7] = pk2(G1.w, G1.w);
        pw2[0] = pk2(P0.x, P0.x); pw2[1] = pk2(P0.y, P0.y);
        pw2[2] = pk2(P0.z, P0.z); pw2[3] = pk2(P0.w, P0.w);
        pw2[4] = pk2(P1.x, P1.x); pw2[5] = pk2(P1.y, P1.y);
        pw2[6] = pk2(P1.z, P1.z); pw2[7] = pk2(P1.w, P1.w);
        #pragma unroll
        for (int kp = 0; kp < 2; kp++) {
            #pragma unroll
            for (int o = 0; o < 8; o++) {
                fma2(ga2[kp][o], x2[kp], gw2[o]);
                fma2(pa2[kp][o], x2[kp], pw2[o]);
            }
        }
        if (wid == 0) {   // warp 0: a[i] = vt . x[:,i]  (collapsed theta)
            float v = vt_s[Ci];
            unsigned long long v2 = pk2(v, v);
            fma2(aa2[0], x2[0], v2);
            fma2(aa2[1], x2[1], v2);
        }
    }

    // bias, maxpool z-pairs (max commutes past +bias), pre-scale gp by 1/64
    {
        const int oc = wid * 8;
        const int j0 = lane * 2, j1 = lane * 2 + 1;
        float part0 = 0.f, part1 = 0.f;
        #pragma unroll
        for (int o = 0; o < 8; o++) {
            float gb = gb_s[oc + o], pb = pb_s[oc + o];
            float2 gA = upk2(ga2[0][o]), gB = upk2(ga2[1][o]);
            gp[j0 * 64 + oc + o] = (fmaxf(gA.x, gA.y) + gb) * 0.015625f;
            gp[j1 * 64 + oc + o] = (fmaxf(gB.x, gB.y) + gb) * 0.015625f;
            float2 pA = upk2(pa2[0][o]), pB = upk2(pa2[1][o]);
            float wpv = wp_s[oc + o];
            part0 = fmaf(wpv, fmaxf(pA.x, pA.y) + pb, part0);
            part1 = fmaf(wpv, fmaxf(pB.x, pB.y) + pb, part1);
        }
        bbp[wid * 64 + j0] = part0;
        bbp[wid * 64 + j1] = part1;
        if (wid == 0) {
            float ct = d_ct;
            float2 a01 = upk2(aa2[0]), a23 = upk2(aa2[1]);
            a_s[lane * 4 + 0] = a01.x + ct;
            a_s[lane * 4 + 1] = a01.y + ct;
            a_s[lane * 4 + 2] = a23.x + ct;
            a_s[lane * 4 + 3] = a23.y + ct;
        }
    }
    __syncthreads();

    if (tid < 64) {  // deterministic reduction of bb over the 8 warps
        float s = 0.f;
        #pragma unroll
        for (int w8 = 0; w8 < 8; w8++) s += bbp[w8 * 64 + tid];
        bb_s[tid] = s;
    }
    __syncthreads();

    // ---- stage C: y[i][c] = sum_j relu(a[i]+bb[j]) * gp[j][c]  (gp pre-scaled) ----
    // warp wid -> c = wid*8..+7 (4 packed c-pairs) ; lane -> i = 4*lane..+3
    {
        unsigned long long ya2[4][4];   // [k][cpair]
        #pragma unroll
        for (int k = 0; k < 4; k++)
            #pragma unroll
            for (int cp = 0; cp < 4; cp++) ya2[k][cp] = 0ULL;

        float4 av = ((const float4*)a_s)[lane];
        float ak[4] = {av.x, av.y, av.z, av.w};

        #pragma unroll 4
        for (int j = 0; j < 64; j++) {
            float bj = bb_s[j];
            unsigned long long f2_[4];
            #pragma unroll
            for (int k = 0; k < 4; k++) {
                float f = fmaxf(ak[k] + bj, 0.f);
                f2_[k] = pk2(f, f);
            }
            ulonglong2 q0 = *(const ulonglong2*)&gp4[j * 16 + (wid << 1)];
            ulonglong2 q1 = *(const ulonglong2*)&gp4[j * 16 + (wid << 1) + 1];
            unsigned long long gv2[4] = {q0.x, q0.y, q1.x, q1.y};
            #pragma unroll
            for (int k = 0; k < 4; k++)
                #pragma unroll
                for (int cp = 0; cp < 4; cp++)
                    fma2(ya2[k][cp], f2_[k], gv2[cp]);
        }
        const int ocy = wid * 8;
        #pragma unroll
        for (int cp = 0; cp < 4; cp++) {   // ys stored transposed: [c][i], i contiguous
            float2 e0 = upk2(ya2[0][cp]), e1 = upk2(ya2[1][cp]);
            float2 e2 = upk2(ya2[2][cp]), e3 = upk2(ya2[3][cp]);
            ys4[(ocy + 2 * cp)     * 32 + lane] = make_float4(e0.x, e1.x, e2.x, e3.x);
            ys4[(ocy + 2 * cp + 1) * 32 + lane] = make_float4(e0.y, e1.y, e2.y, e3.y);
        }
    }
    __syncthreads();

    // ---- stage D: out[Co][i] = alpha[Co]*(sum_c W[Co][c]*y[i][c]) + beta[Co] + x[Co][i]
    // warp wid -> Co = wid*16..+15 ; lane -> i = 4*lane..+3 (2 packed i-pairs)
    {
        unsigned long long oa2[16][2];
        #pragma unroll
        for (int cc = 0; cc < 16; cc++) { oa2[cc][0] = 0ULL; oa2[cc][1] = 0ULL; }

        #pragma unroll 2
        for (int c = 0; c < 64; c++) {
            ulonglong2 yq = *(const ulonglong2*)&ys4[c * 32 + lane];
            unsigned long long y2[2] = {yq.x, yq.y};
            float4 w0 = WwT4[c * 32 + (wid << 2)];
            float4 w1 = WwT4[c * 32 + (wid << 2) + 1];
            float4 w2 = WwT4[c * 32 + (wid << 2) + 2];
            float4 w3 = WwT4[c * 32 + (wid << 2) + 3];
            float wv[16] = {w0.x, w0.y, w0.z, w0.w, w1.x, w1.y, w1.z, w1.w,
                            w2.x, w2.y, w2.z, w2.w, w3.x, w3.y, w3.z, w3.w};
            unsigned long long wp2[16];
            #pragma unroll
            for (int cc = 0; cc < 16; cc++) wp2[cc] = pk2(wv[cc], wv[cc]);
            #pragma unroll
            for (int cc = 0; cc < 16; cc++) {
                fma2(oa2[cc][0], wp2[cc], y2[0]);
                fma2(oa2[cc][1], wp2[cc], y2[1]);
            }
        }

        float4* out4 = (float4*)out;
        const int Cb = wid * 16;
        #pragma unroll
        for (int cc = 0; cc < 16; cc++) {
            int Co = Cb + cc;
            float al = al_s[Co], be = be_s[Co];
            float4 xv = xs4[Co * 32 + lane];  // residual
            float2 p0 = upk2(oa2[cc][0]), p1 = upk2(oa2[cc][1]);
            float4 r;
            r.x = fmaf(p0.x, al, be) + xv.x;
            r.y = fmaf(p0.y, al, be) + xv.y;
            r.z = fmaf(p1.x, al, be) + xv.z;
            r.w = fmaf(p1.y, al, be) + xv.w;
            size_t obase = ((size_t)(b * 128 + Co) * 1024 + wh) * 32 + lane;
            out4[obase] = r;
        }
    }
}

extern "C" void kernel_launch(void* const* d_in, const int* in_sizes, int n_in,
                              void* d_out, int out_size)
{
    const float* x       = (const float*)d_in[0];
    const float* g_w     = (const float*)d_in[1];
    const float* g_b     = (const float*)d_in[2];
    const float* theta_w = (const float*)d_in[3];
    const float* theta_b = (const float*)d_in[4];
    const float* phi_w   = (const float*)d_in[5];
    const float* phi_b   = (const float*)d_in[6];
    const float* cat_w   = (const float*)d_in[7];
    const float* W_w     = (const float*)d_in[8];
    const float* W_b     = (const float*)d_in[9];
    const float* bn_g    = (const float*)d_in[10];
    const float* bn_b    = (const float*)d_in[11];
    const float* bn_m    = (const float*)d_in[12];
    const float* bn_v    = (const float*)d_in[13];

    cudaFuncSetAttribute(nonlocal_kernel,
                         cudaFuncAttributeMaxDynamicSharedMemorySize, SMEM_BYTES);

    setup_kernel<<<1, 256>>>(theta_w, theta_b, cat_w, W_b,
                             bn_g, bn_b, bn_m, bn_v, g_w, phi_w, W_w);
    nonlocal_kernel<<<N_TILES, THREADS, SMEM_BYTES>>>(x, g_b, phi_b, cat_w,
                                                      (float*)d_out);
}